// round 5
// baseline (speedup 1.0000x reference)
#include <cuda_runtime.h>

// GConvLSTM (ChebConv K=1) fused cell + linear head.
// Weights in __constant__ memory (uniform-port LDCU, no shared crossbar cost).
// NPT=1: with uniform weight loads there is nothing to amortize per-thread, so
// spend registers on occupancy instead (256 thr, 2 CTAs/SM, 16 warps/SM).

#define FIN   8
#define HDIM  32
#define OUTD  9
#define KTOT  (FIN + HDIM)   // 40 floats per (gate, channel) weight row
#define KPAIR (KTOT / 2)     // 20 f32x2 pairs
#define TPB   256

// ---------------- constant-packed parameters ----------------
struct __align__(16) CPack {
    float W[4][HDIM][KTOT];   // [gate][j][k]: k<8 = Wx col j, k>=8 = Wh col j
    float B[4][HDIM];         // bx + bh + b combined
    float C[4][HDIM];         // peephole (gate 2 = zeros)
    float L[HDIM][12];        // Wl rows padded 9 -> 12
    float Bl[12];
};

__constant__ __align__(16) CPack cPK;
__device__   __align__(16) CPack g_stage;

// ---------------- fast math helpers (MUFU) ----------------
__device__ __forceinline__ float fast_ex2(float x) {
    float r; asm("ex2.approx.f32 %0, %1;" : "=f"(r) : "f"(x)); return r;
}
__device__ __forceinline__ float fast_rcp(float x) {
    float r; asm("rcp.approx.f32 %0, %1;" : "=f"(r) : "f"(x)); return r;
}
__device__ __forceinline__ float sigmoid_f(float v) {
    return fast_rcp(1.0f + fast_ex2(-1.4426950408889634f * v));
}
__device__ __forceinline__ float tanh_f(float v) {
    return 1.0f - 2.0f * fast_rcp(1.0f + fast_ex2(2.8853900817779268f * v));
}

// ---------------- packed f32x2 helpers ----------------
__device__ __forceinline__ void ffma2(unsigned long long& acc,
                                      unsigned long long a,
                                      unsigned long long b) {
    asm("fma.rn.f32x2 %0, %1, %2, %0;" : "+l"(acc) : "l"(a), "l"(b));
}
__device__ __forceinline__ void unpack2(unsigned long long v, float& lo, float& hi) {
    unsigned int a, b;
    asm("mov.b64 {%0, %1}, %2;" : "=r"(a), "=r"(b) : "l"(v));
    lo = __uint_as_float(a);
    hi = __uint_as_float(b);
}
__device__ __forceinline__ unsigned long long pack2(float lo, float hi) {
    unsigned long long v;
    asm("mov.b64 %0, {%1, %2};" : "=l"(v) : "r"(__float_as_uint(lo)), "r"(__float_as_uint(hi)));
    return v;
}

struct PrepArgs {
    const float* Wx[4];
    const float* bx[4];
    const float* Wh[4];
    const float* bh[4];
    const float* b[4];
    const float* wc[4];   // wc[2] unused
    const float* Wl;
    const float* bl;
};

__global__ void prep_kernel(PrepArgs A) {
    const int tid = threadIdx.x;
    for (int idx = tid; idx < 4 * HDIM * KTOT; idx += blockDim.x) {
        int g = idx / (HDIM * KTOT);
        int r = idx % (HDIM * KTOT);
        int j = r / KTOT, k = r % KTOT;
        g_stage.W[g][j][k] = (k < FIN) ? A.Wx[g][k * HDIM + j]
                                       : A.Wh[g][(k - FIN) * HDIM + j];
    }
    for (int idx = tid; idx < 4 * HDIM; idx += blockDim.x) {
        int g = idx / HDIM, j = idx % HDIM;
        g_stage.B[g][j] = A.bx[g][j] + A.bh[g][j] + A.b[g][j];
        g_stage.C[g][j] = (g == 2) ? 0.0f : A.wc[g][j];
    }
    for (int idx = tid; idx < HDIM * 12; idx += blockDim.x) {
        int j = idx / 12, m = idx % 12;
        g_stage.L[j][m] = (m < OUTD) ? A.Wl[j * OUTD + m] : 0.0f;
    }
    if (tid < 12) g_stage.Bl[tid] = (tid < OUTD) ? A.bl[tid] : 0.0f;
}

struct Params {
    const float* x;
    const float* h;
    const float* c;
    float* y;
    float* h0;
    float* c0;
    int N;
};

__global__ void __launch_bounds__(TPB, 2)
gconv_lstm_kernel(Params P) {
    const int n = blockIdx.x * TPB + threadIdx.x;
    if (n >= P.N) return;

    // ---- load x (8) and h (32) as f32x2 pairs ----
    unsigned long long in2[KPAIR];
    {
        const ulonglong2* xp = (const ulonglong2*)(P.x + (size_t)n * FIN);
        ulonglong2 t0 = xp[0], t1 = xp[1];
        in2[0] = t0.x; in2[1] = t0.y; in2[2] = t1.x; in2[3] = t1.y;
        const ulonglong2* hp = (const ulonglong2*)(P.h + (size_t)n * HDIM);
#pragma unroll
        for (int i = 0; i < 8; i++) {
            ulonglong2 t = hp[i];
            in2[4 + 2 * i] = t.x;
            in2[5 + 2 * i] = t.y;
        }
    }
    const float4* c4  = (const float4*)(P.c  + (size_t)n * HDIM);
    float4*       oh4 = (float4*)      (P.h0 + (size_t)n * HDIM);
    float4*       oc4 = (float4*)      (P.c0 + (size_t)n * HDIM);

    // y accumulators packed as f32x2 (5 pairs = 9 outputs + 1 pad)
    unsigned long long yacc[5];
    {
        const unsigned long long* blp = (const unsigned long long*)cPK.Bl;
#pragma unroll
        for (int m = 0; m < 5; m++) yacc[m] = blp[m];
    }

#pragma unroll 1
    for (int jq = 0; jq < HDIM / 4; jq++) {
        float4 cq = c4[jq];
        float cj[4] = {cq.x, cq.y, cq.z, cq.w};
        float h0q[4], c0q[4];

#pragma unroll
        for (int u = 0; u < 4; u++) {
            const int j = jq * 4 + u;
            float s[4];
#pragma unroll
            for (int g = 0; g < 4; g++) {
                const ulonglong2* wr = (const ulonglong2*)&cPK.W[g][j][0];
                unsigned long long a0 = 0ULL, b0 = 0ULL;
#pragma unroll
                for (int kk = 0; kk < KPAIR / 2; kk++) {   // uniform const loads
                    ulonglong2 w = wr[kk];
                    ffma2(a0, in2[2 * kk + 0], w.x);
                    ffma2(b0, in2[2 * kk + 1], w.y);
                }
                float l0, h0f, l1, h1f;
                unpack2(a0, l0, h0f); unpack2(b0, l1, h1f);
                s[g] = (l0 + h0f) + (l1 + h1f) + cPK.B[g][j];
            }
            const float cv = cj[u];
            float ig = sigmoid_f(s[0] + cPK.C[0][j] * cv);
            float fg = sigmoid_f(s[1] + cPK.C[1][j] * cv);
            float tg = tanh_f(s[2]);
            float cc = fg * cv + ig * tg;
            float og = sigmoid_f(s[3] + cPK.C[3][j] * cc);
            float hh = og * tanh_f(cc);
            c0q[u] = cc;
            h0q[u] = hh;
            float r = fmaxf(hh, 0.0f);
            unsigned long long rr = pack2(r, r);
            const ulonglong2* lwv = (const ulonglong2*)&cPK.L[j][0];
            ulonglong2 lw01 = lwv[0], lw23 = lwv[1];
            unsigned long long lw4 = ((const unsigned long long*)&cPK.L[j][8])[0];
            ffma2(yacc[0], rr, lw01.x);
            ffma2(yacc[1], rr, lw01.y);
            ffma2(yacc[2], rr, lw23.x);
            ffma2(yacc[3], rr, lw23.y);
            ffma2(yacc[4], rr, lw4);
        }
        oh4[jq] = make_float4(h0q[0], h0q[1], h0q[2], h0q[3]);
        oc4[jq] = make_float4(c0q[0], c0q[1], c0q[2], c0q[3]);
    }

    // ---- store y ----
    {
        float* oy = P.y + (size_t)n * OUTD;
        float a, b;
#pragma unroll
        for (int m = 0; m < 4; m++) {
            unpack2(yacc[m], a, b);
            oy[2 * m] = a; oy[2 * m + 1] = b;
        }
        unpack2(yacc[4], a, b);
        oy[8] = a;
    }
}

extern "C" void kernel_launch(void* const* d_in, const int* in_sizes, int n_in,
                              void* d_out, int out_size) {
    (void)n_in; (void)out_size;

    PrepArgs A;
    const int wx_idx[4] = {5, 11, 17, 22};   // gate order: i, f, c, o
    for (int g = 0; g < 4; g++) {
        int base = wx_idx[g];
        A.Wx[g] = (const float*)d_in[base + 0];
        A.bx[g] = (const float*)d_in[base + 1];
        A.Wh[g] = (const float*)d_in[base + 2];
        A.bh[g] = (const float*)d_in[base + 3];
        A.b[g]  = (const float*)d_in[base + 4];
        A.wc[g] = (g == 2) ? A.b[g] : (const float*)d_in[base + 5];  // dummy for gate c
    }
    A.Wl = (const float*)d_in[28];
    A.bl = (const float*)d_in[29];

    Params P;
    P.x = (const float*)d_in[0];
    // d_in[1] = edge_index, d_in[2] = edge_weight: unused (ChebConv K=1)
    P.h = (const float*)d_in[3];
    P.c = (const float*)d_in[4];

    const int N = in_sizes[0] / FIN;
    P.N = N;
    float* out = (float*)d_out;
    P.y  = out;
    P.h0 = out + (size_t)N * OUTD;
    P.c0 = out + (size_t)N * (OUTD + HDIM);

    prep_kernel<<<1, 256>>>(A);
    void* stage_ptr = nullptr;
    cudaGetSymbolAddress(&stage_ptr, g_stage);
    cudaMemcpyToSymbolAsync(cPK, stage_ptr, sizeof(CPack), 0,
                            cudaMemcpyDeviceToDevice, 0);

    const int grid = (N + TPB - 1) / TPB;
    gconv_lstm_kernel<<<grid, TPB>>>(P);
}

// round 7
// speedup vs baseline: 2.3625x; 2.3625x over previous
#include <cuda_runtime.h>
#include <cuda_bf16.h>
#include <cstdint>

// GConvLSTM (ChebConv K=1) fused cell + head via warp-level mma.sync bf16
// (plain PTX — harness compiles at compute_103, so tcgen05 is unavailable).
// Gate GEMM per block: [128 nodes x 48] @ [48 x 128 gate-ch], hi/lo bf16
// split (3 passes) for ~1e-6 precision. B fragments are prepacked in mma
// lane order by a prep kernel. Epilogue is shuffle-free for the LSTM part.

#define FIN   8
#define HDIM  32
#define OUTD  9
#define TPB   128
#define NPB   128          // nodes per block
#define K48   48           // padded K (41 used: 8 x + 32 h + 1 bias)

// dynamic smem layout (bytes)
#define SM_A_HI 0                       // 128 rows x 128B (64 bf16, swizzled)
#define SM_A_LO 16384
#define SM_B    32768                   // 2 var x 3 ks x 16 n x 32 lanes x 8B = 24576
#define SM_EPI  57344
// EpiT = 3*32*4 + 32*12*4 + 12*4 = 1968
#define SM_TOTAL (57344 + 1968)

struct EpiT {
    float wci[HDIM], wcf[HDIM], wco[HDIM];
    float Wl[HDIM][12];
    float bl[12];
};
__device__ __align__(16) uint32_t g_Bfrag[6144];   // [v][ks][n][lane][2]
__device__ __align__(16) EpiT     g_epi;

// ---------------- math helpers ----------------
__device__ __forceinline__ float fast_ex2(float x) {
    float r; asm("ex2.approx.f32 %0, %1;" : "=f"(r) : "f"(x)); return r;
}
__device__ __forceinline__ float fast_rcp(float x) {
    float r; asm("rcp.approx.f32 %0, %1;" : "=f"(r) : "f"(x)); return r;
}
__device__ __forceinline__ float sigmoid_f(float v) {
    return fast_rcp(1.0f + fast_ex2(-1.4426950408889634f * v));
}
__device__ __forceinline__ float tanh_f(float v) {
    return 1.0f - 2.0f * fast_rcp(1.0f + fast_ex2(2.8853900817779268f * v));
}
__device__ __forceinline__ float shfl_bfly(float v, int m) {
    float r;
    asm volatile("shfl.sync.bfly.b32 %0, %1, %2, 0x1f, 0xffffffff;"
                 : "=f"(r) : "f"(v), "r"(m));
    return r;
}
// split (f0,f1) into packed bf16x2 hi and lo(residual)
__device__ __forceinline__ void split2(float f0, float f1, uint32_t& hi, uint32_t& lo) {
    __nv_bfloat16 h0 = __float2bfloat16_rn(f0), h1 = __float2bfloat16_rn(f1);
    float r0 = f0 - __bfloat162float(h0), r1 = f1 - __bfloat162float(h1);
    __nv_bfloat16 l0 = __float2bfloat16_rn(r0), l1 = __float2bfloat16_rn(r1);
    hi = ((uint32_t)__bfloat16_as_ushort(h1) << 16) | __bfloat16_as_ushort(h0);
    lo = ((uint32_t)__bfloat16_as_ushort(l1) << 16) | __bfloat16_as_ushort(l0);
}
__device__ __forceinline__ void mma16816(float c[4], const uint32_t a[4],
                                         const uint32_t b[2]) {
    asm volatile(
        "mma.sync.aligned.m16n8k16.row.col.f32.bf16.bf16.f32 "
        "{%0,%1,%2,%3}, {%4,%5,%6,%7}, {%8,%9}, {%0,%1,%2,%3};"
        : "+f"(c[0]), "+f"(c[1]), "+f"(c[2]), "+f"(c[3])
        : "r"(a[0]), "r"(a[1]), "r"(a[2]), "r"(a[3]), "r"(b[0]), "r"(b[1]));
}
__device__ __forceinline__ void lstm_pw(float si, float sf, float sc, float so,
                                        float cv, float wi, float wf, float wo,
                                        float& hh, float& cc) {
    float ig = sigmoid_f(si + wi * cv);
    float fg = sigmoid_f(sf + wf * cv);
    float tg = tanh_f(sc);
    cc = fg * cv + ig * tg;
    float og = sigmoid_f(so + wo * cc);
    hh = og * tanh_f(cc);
}

// ---------------- prep kernel ----------------
struct PrepArgs {
    const float* Wx[4];
    const float* bx[4];
    const float* Wh[4];
    const float* bh[4];
    const float* b[4];
    const float* wc[4];   // wc[2] dummy
    const float* Wl;
    const float* bl;
};

__global__ void prep_kernel(PrepArgs A) {
    // B fragments in exact mma.m16n8k16 lane order.
    // gatech = n*8 + (lane>>2); k rows = ks*16 + (lane&3)*2 + r*8 + {0,1}
    for (int idx = threadIdx.x; idx < 6144; idx += blockDim.x) {
        int r    = idx & 1;
        int lane = (idx >> 1) & 31;
        int rest = idx >> 6;
        int n  = rest & 15; rest >>= 4;
        int ks = rest % 3;
        int v  = rest / 3;
        int gatech = n * 8 + (lane >> 2);
        int g = gatech >> 5, j = gatech & 31;
        int k0 = ks * 16 + (lane & 3) * 2 + r * 8;
        uint32_t w = 0;
        for (int e = 0; e < 2; e++) {
            int k = k0 + e;
            float val = 0.f;
            if (k < FIN)      val = A.Wx[g][k * HDIM + j];
            else if (k < 40)  val = A.Wh[g][(k - FIN) * HDIM + j];
            else if (k == 40) val = A.bx[g][j] + A.bh[g][j] + A.b[g][j];
            __nv_bfloat16 hi = __float2bfloat16_rn(val);
            __nv_bfloat16 ov = (v == 0) ? hi
                : __float2bfloat16_rn(val - __bfloat162float(hi));
            w |= (uint32_t)__bfloat16_as_ushort(ov) << (16 * e);
        }
        g_Bfrag[idx] = w;
    }
    for (int j = threadIdx.x; j < HDIM; j += blockDim.x) {
        g_epi.wci[j] = A.wc[0][j];
        g_epi.wcf[j] = A.wc[1][j];
        g_epi.wco[j] = A.wc[3][j];
        for (int m = 0; m < 12; m++)
            g_epi.Wl[j][m] = (m < OUTD) ? A.Wl[j * OUTD + m] : 0.f;
    }
    if (threadIdx.x < 12)
        g_epi.bl[threadIdx.x] = (threadIdx.x < OUTD) ? A.bl[threadIdx.x] : 0.f;
}

// ---------------- main kernel ----------------
struct Params {
    const float* x;
    const float* h;
    const float* c;
    float* y;
    float* h0;
    float* c0;
    int N;
};

__global__ void __launch_bounds__(TPB)
gconv_lstm_mma_kernel(Params P) {
    extern __shared__ __align__(16) char smem[];
    const int tid = threadIdx.x;

    // ---- stage B fragments + epilogue tables ----
    {
        const uint4* src = (const uint4*)g_Bfrag;
        uint4* dst = (uint4*)(smem + SM_B);
        for (int i = tid; i < 6144 / 4; i += TPB) dst[i] = src[i];
        const uint32_t* es = (const uint32_t*)&g_epi;
        uint32_t* ed = (uint32_t*)(smem + SM_EPI);
        for (int i = tid; i < (int)(sizeof(EpiT) / 4); i += TPB) ed[i] = es[i];
    }

    // ---- stage this thread's node row as A hi/lo (swizzled 128B rows) ----
    {
        const int sNode = blockIdx.x * NPB + tid;
        const int cls   = (sNode < P.N) ? sNode : (P.N - 1);
        float v[K48];
#pragma unroll
        for (int i = 0; i < K48; i++) v[i] = 0.f;
        const float4* xp = (const float4*)(P.x + (size_t)cls * FIN);
        float4 x0 = xp[0], x1 = xp[1];
        v[0]=x0.x; v[1]=x0.y; v[2]=x0.z; v[3]=x0.w;
        v[4]=x1.x; v[5]=x1.y; v[6]=x1.z; v[7]=x1.w;
        const float4* hp = (const float4*)(P.h + (size_t)cls * HDIM);
#pragma unroll
        for (int i = 0; i < 8; i++) {
            float4 hv = hp[i];
            v[8+4*i]=hv.x; v[9+4*i]=hv.y; v[10+4*i]=hv.z; v[11+4*i]=hv.w;
        }
        v[40] = 1.0f;   // bias column
#pragma unroll
        for (int i = 0; i < 8; i++) {
            uint32_t hw[4], lw[4];
#pragma unroll
            for (int p = 0; p < 4; p++) {
                int c0 = i * 8 + p * 2;
                float f0 = (c0     < K48) ? v[c0]     : 0.f;
                float f1 = (c0 + 1 < K48) ? v[c0 + 1] : 0.f;
                split2(f0, f1, hw[p], lw[p]);
            }
            uint32_t off = tid * 128 + ((i * 16) ^ ((tid & 7) << 4));
            *(uint4*)(smem + SM_A_HI + off) = make_uint4(hw[0], hw[1], hw[2], hw[3]);
            *(uint4*)(smem + SM_A_LO + off) = make_uint4(lw[0], lw[1], lw[2], lw[3]);
        }
    }
    __syncthreads();

    const EpiT* E = (const EpiT*)(smem + SM_EPI);
    const int lane = tid & 31, warp = tid >> 5;
    const int g = lane >> 2, q = lane & 3;

#pragma unroll 1
    for (int t = 0; t < 2; t++) {
        const int rbase = warp * 32 + t * 16;      // staging row base of tile
        const int r0 = rbase + g, r1 = r0 + 8;

        // ---- A fragments (hi & lo), kept across all 16 n-steps ----
        uint32_t ah[3][4], al[3][4];
#pragma unroll
        for (int ks = 0; ks < 3; ks++) {
            const int b0 = ks * 32 + q * 4;
            const int x0h = (r0 & 7) << 4, x1h = (r1 & 7) << 4;
            ah[ks][0] = *(const uint32_t*)(smem + SM_A_HI + r0*128 + ( b0       ^ x0h));
            ah[ks][1] = *(const uint32_t*)(smem + SM_A_HI + r1*128 + ( b0       ^ x1h));
            ah[ks][2] = *(const uint32_t*)(smem + SM_A_HI + r0*128 + ((b0 + 16) ^ x0h));
            ah[ks][3] = *(const uint32_t*)(smem + SM_A_HI + r1*128 + ((b0 + 16) ^ x1h));
            al[ks][0] = *(const uint32_t*)(smem + SM_A_LO + r0*128 + ( b0       ^ x0h));
            al[ks][1] = *(const uint32_t*)(smem + SM_A_LO + r1*128 + ( b0       ^ x1h));
            al[ks][2] = *(const uint32_t*)(smem + SM_A_LO + r0*128 + ((b0 + 16) ^ x0h));
            al[ks][3] = *(const uint32_t*)(smem + SM_A_LO + r1*128 + ((b0 + 16) ^ x1h));
        }

        // ---- 16 n-steps x (3 passes x 3 ksteps) mma ----
        float acc[16][4];
#pragma unroll
        for (int n = 0; n < 16; n++) {
            acc[n][0] = acc[n][1] = acc[n][2] = acc[n][3] = 0.f;
            uint32_t bh[3][2], bl2[3][2];
#pragma unroll
            for (int ks = 0; ks < 3; ks++) {
                uint2 hv = *(const uint2*)(smem + SM_B + ((ks*16 + n)*32 + lane)*8);
                uint2 lv = *(const uint2*)(smem + SM_B + (((3+ks)*16 + n)*32 + lane)*8);
                bh[ks][0] = hv.x; bh[ks][1] = hv.y;
                bl2[ks][0] = lv.x; bl2[ks][1] = lv.y;
            }
#pragma unroll
            for (int ks = 0; ks < 3; ks++) mma16816(acc[n], ah[ks], bh[ks]);
#pragma unroll
            for (int ks = 0; ks < 3; ks++) mma16816(acc[n], ah[ks], bl2[ks]);
#pragma unroll
            for (int ks = 0; ks < 3; ks++) mma16816(acc[n], al[ks], bh[ks]);
        }

        // ---- epilogue: thread owns nodes (node0, node1), channels j0..j0+1 per nl ----
        const int node0 = blockIdx.x * NPB + rbase + g;
        const int node1 = node0 + 8;
        const bool v0 = (node0 < P.N), v1 = (node1 < P.N);
        const int ci0 = v0 ? node0 : (P.N - 1);
        const int ci1 = v1 ? node1 : (P.N - 1);

        float y0[OUTD], y1[OUTD];
#pragma unroll
        for (int m = 0; m < OUTD; m++) { y0[m] = 0.f; y1[m] = 0.f; }

#pragma unroll
        for (int nl = 0; nl < 4; nl++) {
            const int j0 = nl * 8 + q * 2;
            float2 cva = *(const float2*)(P.c + (size_t)ci0 * HDIM + j0);
            float2 cvb = *(const float2*)(P.c + (size_t)ci1 * HDIM + j0);
            float2 wiv = *(const float2*)(&E->wci[j0]);
            float2 wfv = *(const float2*)(&E->wcf[j0]);
            float2 wov = *(const float2*)(&E->wco[j0]);
            float4 wa0 = *(const float4*)(&E->Wl[j0][0]);
            float4 wb0 = *(const float4*)(&E->Wl[j0][4]);
            float  wc0 = E->Wl[j0][8];
            float4 wa1 = *(const float4*)(&E->Wl[j0 + 1][0]);
            float4 wb1 = *(const float4*)(&E->Wl[j0 + 1][4]);
            float  wc1 = E->Wl[j0 + 1][8];

            float ha, ca, hb, cb;
            lstm_pw(acc[nl][0], acc[nl+4][0], acc[nl+8][0], acc[nl+12][0],
                    cva.x, wiv.x, wfv.x, wov.x, ha, ca);
            lstm_pw(acc[nl][1], acc[nl+4][1], acc[nl+8][1], acc[nl+12][1],
                    cva.y, wiv.y, wfv.y, wov.y, hb, cb);
            if (v0) {
                *(float2*)(P.h0 + (size_t)node0 * HDIM + j0) = make_float2(ha, hb);
                *(float2*)(P.c0 + (size_t)node0 * HDIM + j0) = make_float2(ca, cb);
            }
            float ra = fmaxf(ha, 0.f), rb = fmaxf(hb, 0.f);
            y0[0]+=ra*wa0.x+rb*wa1.x; y0[1]+=ra*wa0.y+rb*wa1.y;
            y0[2]+=ra*wa0.z+rb*wa1.z; y0[3]+=ra*wa0.w+rb*wa1.w;
            y0[4]+=ra*wb0.x+rb*wb1.x; y0[5]+=ra*wb0.y+rb*wb1.y;
            y0[6]+=ra*wb0.z+rb*wb1.z; y0[7]+=ra*wb0.w+rb*wb1.w;
            y0[8]+=ra*wc0  +rb*wc1;

            lstm_pw(acc[nl][2], acc[nl+4][2], acc[nl+8][2], acc[nl+12][2],
                    cvb.x, wiv.x, wfv.x, wov.x, ha, ca);
            lstm_pw(acc[nl][3], acc[nl+4][3], acc[nl+8][3], acc[nl+12][3],
                    cvb.y, wiv.y, wfv.y, wov.y, hb, cb);
            if (v1) {
                *(float2*)(P.h0 + (size_t)node1 * HDIM + j0) = make_float2(ha, hb);
                *(float2*)(P.c0 + (size_t)node1 * HDIM + j0) = make_float2(ca, cb);
            }
            ra = fmaxf(ha, 0.f); rb = fmaxf(hb, 0.f);
            y1[0]+=ra*wa0.x+rb*wa1.x; y1[1]+=ra*wa0.y+rb*wa1.y;
            y1[2]+=ra*wa0.z+rb*wa1.z; y1[3]+=ra*wa0.w+rb*wa1.w;
            y1[4]+=ra*wb0.x+rb*wb1.x; y1[5]+=ra*wb0.y+rb*wb1.y;
            y1[6]+=ra*wb0.z+rb*wb1.z; y1[7]+=ra*wb0.w+rb*wb1.w;
            y1[8]+=ra*wc0  +rb*wc1;
        }

        // ---- y: butterfly-reduce over the 4-lane quad, distributed store ----
#pragma unroll
        for (int m = 0; m < OUTD; m++) {
            y0[m] += shfl_bfly(y0[m], 1); y0[m] += shfl_bfly(y0[m], 2);
            y1[m] += shfl_bfly(y1[m], 1); y1[m] += shfl_bfly(y1[m], 2);
        }
        if (v0) {
            float* oy = P.y + (size_t)node0 * OUTD;
            oy[q]     = y0[q]     + E->bl[q];
            oy[q + 4] = y0[q + 4] + E->bl[q + 4];
            if (q == 0) oy[8] = y0[8] + E->bl[8];
        }
        if (v1) {
            float* oy = P.y + (size_t)node1 * OUTD;
            oy[q]     = y1[q]     + E->bl[q];
            oy[q + 4] = y1[q + 4] + E->bl[q + 4];
            if (q == 0) oy[8] = y1[8] + E->bl[8];
        }
    }
}

extern "C" void kernel_launch(void* const* d_in, const int* in_sizes, int n_in,
                              void* d_out, int out_size) {
    (void)n_in; (void)out_size;

    PrepArgs A;
    const int wx_idx[4] = {5, 11, 17, 22};   // gate order: i, f, c, o
    for (int g = 0; g < 4; g++) {
        int base = wx_idx[g];
        A.Wx[g] = (const float*)d_in[base + 0];
        A.bx[g] = (const float*)d_in[base + 1];
        A.Wh[g] = (const float*)d_in[base + 2];
        A.bh[g] = (const float*)d_in[base + 3];
        A.b[g]  = (const float*)d_in[base + 4];
        A.wc[g] = (g == 2) ? A.b[g] : (const float*)d_in[base + 5];  // dummy for gate c
    }
    A.Wl = (const float*)d_in[28];
    A.bl = (const float*)d_in[29];

    Params P;
    P.x = (const float*)d_in[0];
    // d_in[1] = edge_index, d_in[2] = edge_weight: unused (ChebConv K=1)
    P.h = (const float*)d_in[3];
    P.c = (const float*)d_in[4];

    const int N = in_sizes[0] / FIN;
    P.N = N;
    float* out = (float*)d_out;
    P.y  = out;
    P.h0 = out + (size_t)N * OUTD;
    P.c0 = out + (size_t)N * (OUTD + HDIM);

    prep_kernel<<<1, 256>>>(A);

    cudaFuncSetAttribute(gconv_lstm_mma_kernel,
                         cudaFuncAttributeMaxDynamicSharedMemorySize, SM_TOTAL);
    const int grid = (N + NPB - 1) / NPB;
    gconv_lstm_mma_kernel<<<grid, TPB, SM_TOTAL>>>(P);
}

// round 8
// speedup vs baseline: 3.6842x; 1.5595x over previous
#include <cuda_runtime.h>
#include <cuda_fp16.h>
#include <cstdint>

// GConvLSTM (ChebConv K=1) fused cell + head via warp-level mma.sync fp16
// single-pass (fp16 mantissa gives ~1e-4 output rel err, tolerance 1e-3).
// Gate GEMM per block: [128 nodes x 48] @ [48 x 128 gate-ch].
// B fragments prepacked in mma lane order. Epilogue shuffle-free LSTM.

#define FIN   8
#define HDIM  32
#define OUTD  9
#define TPB   128
#define NPB   128          // nodes per block
#define K48   48           // padded K (41 used: 8 x + 32 h + 1 bias)

// dynamic smem layout (bytes)
#define SM_A    0                        // 128 rows x 128B (fp16, swizzled)
#define SM_B    16384                    // 3 ks x 16 n x 32 lanes x 8B = 12288
#define SM_EPI  (16384 + 12288)          // 28672
// EpiT = 3*32*4 + 32*12*4 + 12*4 = 1968
#define SM_TOTAL (28672 + 1968)

struct EpiT {
    float wci[HDIM], wcf[HDIM], wco[HDIM];
    float Wl[HDIM][12];
    float bl[12];
};
__device__ __align__(16) uint32_t g_Bfrag[3072];   // [ks][n][lane][2] fp16x2
__device__ __align__(16) EpiT     g_epi;

// ---------------- math helpers ----------------
__device__ __forceinline__ float fast_ex2(float x) {
    float r; asm("ex2.approx.f32 %0, %1;" : "=f"(r) : "f"(x)); return r;
}
__device__ __forceinline__ float fast_rcp(float x) {
    float r; asm("rcp.approx.f32 %0, %1;" : "=f"(r) : "f"(x)); return r;
}
__device__ __forceinline__ float sigmoid_f(float v) {
    return fast_rcp(1.0f + fast_ex2(-1.4426950408889634f * v));
}
__device__ __forceinline__ float tanh_f(float v) {
    return 1.0f - 2.0f * fast_rcp(1.0f + fast_ex2(2.8853900817779268f * v));
}
__device__ __forceinline__ float shfl_bfly(float v, int m) {
    float r;
    asm volatile("shfl.sync.bfly.b32 %0, %1, %2, 0x1f, 0xffffffff;"
                 : "=f"(r) : "f"(v), "r"(m));
    return r;
}
__device__ __forceinline__ uint32_t pack_h2(float f0, float f1) {
    __half h0 = __float2half_rn(f0), h1 = __float2half_rn(f1);
    return ((uint32_t)__half_as_ushort(h1) << 16) | __half_as_ushort(h0);
}
__device__ __forceinline__ void mma16816(float c[4], const uint32_t a[4],
                                         const uint32_t b[2]) {
    asm volatile(
        "mma.sync.aligned.m16n8k16.row.col.f32.f16.f16.f32 "
        "{%0,%1,%2,%3}, {%4,%5,%6,%7}, {%8,%9}, {%0,%1,%2,%3};"
        : "+f"(c[0]), "+f"(c[1]), "+f"(c[2]), "+f"(c[3])
        : "r"(a[0]), "r"(a[1]), "r"(a[2]), "r"(a[3]), "r"(b[0]), "r"(b[1]));
}
__device__ __forceinline__ void lstm_pw(float si, float sf, float sc, float so,
                                        float cv, float wi, float wf, float wo,
                                        float& hh, float& cc) {
    float ig = sigmoid_f(si + wi * cv);
    float fg = sigmoid_f(sf + wf * cv);
    float tg = tanh_f(sc);
    cc = fg * cv + ig * tg;
    float og = sigmoid_f(so + wo * cc);
    hh = og * tanh_f(cc);
}

// ---------------- prep kernel ----------------
struct PrepArgs {
    const float* Wx[4];
    const float* bx[4];
    const float* Wh[4];
    const float* bh[4];
    const float* b[4];
    const float* wc[4];   // wc[2] dummy
    const float* Wl;
    const float* bl;
};

__global__ void prep_kernel(PrepArgs A) {
    const int gtid = blockIdx.x * blockDim.x + threadIdx.x;
    const int gstr = gridDim.x * blockDim.x;
    // B fragments in exact mma.m16n8k16 lane order (fp16).
    // gatech = n*8 + (lane>>2); k = ks*16 + (lane&3)*2 + w*8 + e
    for (int idx = gtid; idx < 3072; idx += gstr) {
        int w    = idx & 1;
        int lane = (idx >> 1) & 31;
        int n    = (idx >> 6) & 15;
        int ks   = idx >> 10;
        int gatech = n * 8 + (lane >> 2);
        int g = gatech >> 5, j = gatech & 31;
        int k0 = ks * 16 + (lane & 3) * 2 + w * 8;
        uint32_t out = 0;
        for (int e = 0; e < 2; e++) {
            int k = k0 + e;
            float val = 0.f;
            if (k < FIN)      val = A.Wx[g][k * HDIM + j];
            else if (k < 40)  val = A.Wh[g][(k - FIN) * HDIM + j];
            else if (k == 40) val = A.bx[g][j] + A.bh[g][j] + A.b[g][j];
            out |= (uint32_t)__half_as_ushort(__float2half_rn(val)) << (16 * e);
        }
        g_Bfrag[idx] = out;
    }
    for (int j = gtid; j < HDIM; j += gstr) {
        g_epi.wci[j] = A.wc[0][j];
        g_epi.wcf[j] = A.wc[1][j];
        g_epi.wco[j] = A.wc[3][j];
        for (int m = 0; m < 12; m++)
            g_epi.Wl[j][m] = (m < OUTD) ? A.Wl[j * OUTD + m] : 0.f;
    }
    if (gtid < 12)
        g_epi.bl[gtid] = (gtid < OUTD) ? A.bl[gtid] : 0.f;
}

// ---------------- main kernel ----------------
struct Params {
    const float* x;
    const float* h;
    const float* c;
    float* y;
    float* h0;
    float* c0;
    int N;
};

__global__ void __launch_bounds__(TPB)
gconv_lstm_mma_kernel(Params P) {
    extern __shared__ __align__(16) char smem[];
    const int tid = threadIdx.x;

    // ---- stage B fragments + epilogue tables ----
    {
        const uint4* src = (const uint4*)g_Bfrag;
        uint4* dst = (uint4*)(smem + SM_B);
        for (int i = tid; i < 3072 / 4; i += TPB) dst[i] = src[i];
        const uint32_t* es = (const uint32_t*)&g_epi;
        uint32_t* ed = (uint32_t*)(smem + SM_EPI);
        for (int i = tid; i < (int)(sizeof(EpiT) / 4); i += TPB) ed[i] = es[i];
    }

    // ---- stage this thread's node row as fp16 A (swizzled 128B rows) ----
    {
        const int sNode = blockIdx.x * NPB + tid;
        const int cls   = (sNode < P.N) ? sNode : (P.N - 1);
        float v[K48];
#pragma unroll
        for (int i = 0; i < K48; i++) v[i] = 0.f;
        const float4* xp = (const float4*)(P.x + (size_t)cls * FIN);
        float4 x0 = xp[0], x1 = xp[1];
        v[0]=x0.x; v[1]=x0.y; v[2]=x0.z; v[3]=x0.w;
        v[4]=x1.x; v[5]=x1.y; v[6]=x1.z; v[7]=x1.w;
        const float4* hp = (const float4*)(P.h + (size_t)cls * HDIM);
#pragma unroll
        for (int i = 0; i < 8; i++) {
            float4 hv = hp[i];
            v[8+4*i]=hv.x; v[9+4*i]=hv.y; v[10+4*i]=hv.z; v[11+4*i]=hv.w;
        }
        v[40] = 1.0f;   // bias column
#pragma unroll
        for (int i = 0; i < 6; i++) {        // 6 chunks of 8 values = 48
            uint32_t w[4];
#pragma unroll
            for (int p = 0; p < 4; p++)
                w[p] = pack_h2(v[i * 8 + 2 * p], v[i * 8 + 2 * p + 1]);
            uint32_t off = tid * 128 + ((i * 16) ^ ((tid & 7) << 4));
            *(uint4*)(smem + SM_A + off) = make_uint4(w[0], w[1], w[2], w[3]);
        }
    }
    __syncthreads();

    const EpiT* E = (const EpiT*)(smem + SM_EPI);
    const int lane = tid & 31, warp = tid >> 5;
    const int g = lane >> 2, q = lane & 3;

#pragma unroll 1
    for (int t = 0; t < 2; t++) {
        const int rbase = warp * 32 + t * 16;      // staging row base of tile
        const int r0 = rbase + g, r1 = r0 + 8;

        // ---- A fragments, kept across all 16 n-steps ----
        uint32_t ah[3][4];
#pragma unroll
        for (int ks = 0; ks < 3; ks++) {
            const int b0 = ks * 32 + q * 4;
            const int x0h = (r0 & 7) << 4, x1h = (r1 & 7) << 4;
            ah[ks][0] = *(const uint32_t*)(smem + SM_A + r0*128 + ( b0       ^ x0h));
            ah[ks][1] = *(const uint32_t*)(smem + SM_A + r1*128 + ( b0       ^ x1h));
            ah[ks][2] = *(const uint32_t*)(smem + SM_A + r0*128 + ((b0 + 16) ^ x0h));
            ah[ks][3] = *(const uint32_t*)(smem + SM_A + r1*128 + ((b0 + 16) ^ x1h));
        }

        // ---- 16 n-steps x 3 ksteps mma ----
        float acc[16][4];
#pragma unroll
        for (int n = 0; n < 16; n++) {
            acc[n][0] = acc[n][1] = acc[n][2] = acc[n][3] = 0.f;
            uint32_t bf[3][2];
#pragma unroll
            for (int ks = 0; ks < 3; ks++) {
                uint2 hv = *(const uint2*)(smem + SM_B + ((ks*16 + n)*32 + lane)*8);
                bf[ks][0] = hv.x; bf[ks][1] = hv.y;
            }
#pragma unroll
            for (int ks = 0; ks < 3; ks++) mma16816(acc[n], ah[ks], bf[ks]);
        }

        // ---- epilogue: thread owns nodes (node0, node1), channels j0..j0+1 per nl ----
        const int node0 = blockIdx.x * NPB + rbase + g;
        const int node1 = node0 + 8;
        const bool v0 = (node0 < P.N), v1 = (node1 < P.N);
        const int ci0 = v0 ? node0 : (P.N - 1);
        const int ci1 = v1 ? node1 : (P.N - 1);

        float y0[OUTD], y1[OUTD];
#pragma unroll
        for (int m = 0; m < OUTD; m++) { y0[m] = 0.f; y1[m] = 0.f; }

#pragma unroll
        for (int nl = 0; nl < 4; nl++) {
            const int j0 = nl * 8 + q * 2;
            float2 cva = *(const float2*)(P.c + (size_t)ci0 * HDIM + j0);
            float2 cvb = *(const float2*)(P.c + (size_t)ci1 * HDIM + j0);
            float2 wiv = *(const float2*)(&E->wci[j0]);
            float2 wfv = *(const float2*)(&E->wcf[j0]);
            float2 wov = *(const float2*)(&E->wco[j0]);
            float4 wa0 = *(const float4*)(&E->Wl[j0][0]);
            float4 wb0 = *(const float4*)(&E->Wl[j0][4]);
            float  wc0 = E->Wl[j0][8];
            float4 wa1 = *(const float4*)(&E->Wl[j0 + 1][0]);
            float4 wb1 = *(const float4*)(&E->Wl[j0 + 1][4]);
            float  wc1 = E->Wl[j0 + 1][8];

            float ha, ca, hb, cb;
            lstm_pw(acc[nl][0], acc[nl+4][0], acc[nl+8][0], acc[nl+12][0],
                    cva.x, wiv.x, wfv.x, wov.x, ha, ca);
            lstm_pw(acc[nl][1], acc[nl+4][1], acc[nl+8][1], acc[nl+12][1],
                    cva.y, wiv.y, wfv.y, wov.y, hb, cb);
            if (v0) {
                *(float2*)(P.h0 + (size_t)node0 * HDIM + j0) = make_float2(ha, hb);
                *(float2*)(P.c0 + (size_t)node0 * HDIM + j0) = make_float2(ca, cb);
            }
            float ra = fmaxf(ha, 0.f), rb = fmaxf(hb, 0.f);
            y0[0]+=ra*wa0.x+rb*wa1.x; y0[1]+=ra*wa0.y+rb*wa1.y;
            y0[2]+=ra*wa0.z+rb*wa1.z; y0[3]+=ra*wa0.w+rb*wa1.w;
            y0[4]+=ra*wb0.x+rb*wb1.x; y0[5]+=ra*wb0.y+rb*wb1.y;
            y0[6]+=ra*wb0.z+rb*wb1.z; y0[7]+=ra*wb0.w+rb*wb1.w;
            y0[8]+=ra*wc0  +rb*wc1;

            lstm_pw(acc[nl][2], acc[nl+4][2], acc[nl+8][2], acc[nl+12][2],
                    cvb.x, wiv.x, wfv.x, wov.x, ha, ca);
            lstm_pw(acc[nl][3], acc[nl+4][3], acc[nl+8][3], acc[nl+12][3],
                    cvb.y, wiv.y, wfv.y, wov.y, hb, cb);
            if (v1) {
                *(float2*)(P.h0 + (size_t)node1 * HDIM + j0) = make_float2(ha, hb);
                *(float2*)(P.c0 + (size_t)node1 * HDIM + j0) = make_float2(ca, cb);
            }
            ra = fmaxf(ha, 0.f); rb = fmaxf(hb, 0.f);
            y1[0]+=ra*wa0.x+rb*wa1.x; y1[1]+=ra*wa0.y+rb*wa1.y;
            y1[2]+=ra*wa0.z+rb*wa1.z; y1[3]+=ra*wa0.w+rb*wa1.w;
            y1[4]+=ra*wb0.x+rb*wb1.x; y1[5]+=ra*wb0.y+rb*wb1.y;
            y1[6]+=ra*wb0.z+rb*wb1.z; y1[7]+=ra*wb0.w+rb*wb1.w;
            y1[8]+=ra*wc0  +rb*wc1;
        }

        // ---- y: butterfly-reduce over the 4-lane quad, distributed store ----
#pragma unroll
        for (int m = 0; m < OUTD; m++) {
            y0[m] += shfl_bfly(y0[m], 1); y0[m] += shfl_bfly(y0[m], 2);
            y1[m] += shfl_bfly(y1[m], 1); y1[m] += shfl_bfly(y1[m], 2);
        }
        if (v0) {
            float* oy = P.y + (size_t)node0 * OUTD;
            oy[q]     = y0[q]     + E->bl[q];
            oy[q + 4] = y0[q + 4] + E->bl[q + 4];
            if (q == 0) oy[8] = y0[8] + E->bl[8];
        }
        if (v1) {
            float* oy = P.y + (size_t)node1 * OUTD;
            oy[q]     = y1[q]     + E->bl[q];
            oy[q + 4] = y1[q + 4] + E->bl[q + 4];
            if (q == 0) oy[8] = y1[8] + E->bl[8];
        }
    }
}

extern "C" void kernel_launch(void* const* d_in, const int* in_sizes, int n_in,
                              void* d_out, int out_size) {
    (void)n_in; (void)out_size;

    PrepArgs A;
    const int wx_idx[4] = {5, 11, 17, 22};   // gate order: i, f, c, o
    for (int g = 0; g < 4; g++) {
        int base = wx_idx[g];
        A.Wx[g] = (const float*)d_in[base + 0];
        A.bx[g] = (const float*)d_in[base + 1];
        A.Wh[g] = (const float*)d_in[base + 2];
        A.bh[g] = (const float*)d_in[base + 3];
        A.b[g]  = (const float*)d_in[base + 4];
        A.wc[g] = (g == 2) ? A.b[g] : (const float*)d_in[base + 5];  // dummy for gate c
    }
    A.Wl = (const float*)d_in[28];
    A.bl = (const float*)d_in[29];

    Params P;
    P.x = (const float*)d_in[0];
    // d_in[1] = edge_index, d_in[2] = edge_weight: unused (ChebConv K=1)
    P.h = (const float*)d_in[3];
    P.c = (const float*)d_in[4];

    const int N = in_sizes[0] / FIN;
    P.N = N;
    float* out = (float*)d_out;
    P.y  = out;
    P.h0 = out + (size_t)N * OUTD;
    P.c0 = out + (size_t)N * (OUTD + HDIM);

    prep_kernel<<<16, 256>>>(A);

    cudaFuncSetAttribute(gconv_lstm_mma_kernel,
                         cudaFuncAttributeMaxDynamicSharedMemorySize, SM_TOTAL);
    const int grid = (N + NPB - 1) / NPB;
    gconv_lstm_mma_kernel<<<grid, TPB, SM_TOTAL>>>(P);
}

// round 10
// speedup vs baseline: 4.2841x; 1.1628x over previous
#include <cuda_runtime.h>
#include <cuda_fp16.h>
#include <cstdint>

// GConvLSTM (ChebConv K=1) fused cell + head, warp-level mma.sync fp16.
// R10 = R9 with the misaligned float2 y-store fixed (scalar stores; y rows
// are 9 floats so node*9+2q is odd half the time -> STG.64 trap).
// y-head on tensor cores, ldmatrix A fragments, c prefetched under GEMM.

#define FIN   8
#define HDIM  32
#define OUTD  9
#define TPB   128
#define NPB   128          // nodes per block
#define K48   48           // padded K (41 used: 8 x + 32 h + 1 bias)

// dynamic smem layout (bytes)
#define SM_A    0                        // 128 rows x 128B (fp16, swizzled)
#define SM_B    16384                    // 3 ks x 16 n x 32 lanes x 8B = 12288
#define SM_YB   (16384 + 12288)          // 28672: 2 nt x 2 ks x 32 x 8B = 1024
#define SM_EPI  (28672 + 1024)           // 29696
// EpiT = 3*32*4 + 12*4 = 432
#define SM_TOTAL (29696 + 432)

struct EpiT {
    float wci[HDIM], wcf[HDIM], wco[HDIM];
    float bl[12];
};
__device__ __align__(16) uint32_t g_Bfrag[3072];   // [ks][n][lane][w] fp16x2
__device__ __align__(16) uint32_t g_yB[256];       // [nt][ks][lane][w] fp16x2
__device__ __align__(16) EpiT     g_epi;

// ---------------- math helpers ----------------
__device__ __forceinline__ float fast_ex2(float x) {
    float r; asm("ex2.approx.f32 %0, %1;" : "=f"(r) : "f"(x)); return r;
}
__device__ __forceinline__ float fast_rcp(float x) {
    float r; asm("rcp.approx.f32 %0, %1;" : "=f"(r) : "f"(x)); return r;
}
__device__ __forceinline__ float sigmoid_f(float v) {
    return fast_rcp(1.0f + fast_ex2(-1.4426950408889634f * v));
}
__device__ __forceinline__ float tanh_f(float v) {
    return 1.0f - 2.0f * fast_rcp(1.0f + fast_ex2(2.8853900817779268f * v));
}
__device__ __forceinline__ uint32_t pack_h2(float f0, float f1) {
    __half h0 = __float2half_rn(f0), h1 = __float2half_rn(f1);
    return ((uint32_t)__half_as_ushort(h1) << 16) | __half_as_ushort(h0);
}
__device__ __forceinline__ uint32_t smem_u32(const void* p) {
    uint32_t a;
    asm("{ .reg .u64 t; cvta.to.shared.u64 t, %1; cvt.u32.u64 %0, t; }" : "=r"(a) : "l"(p));
    return a;
}
__device__ __forceinline__ void mma16816(float c[4], const uint32_t a[4],
                                         const uint32_t b[2]) {
    asm volatile(
        "mma.sync.aligned.m16n8k16.row.col.f32.f16.f16.f32 "
        "{%0,%1,%2,%3}, {%4,%5,%6,%7}, {%8,%9}, {%0,%1,%2,%3};"
        : "+f"(c[0]), "+f"(c[1]), "+f"(c[2]), "+f"(c[3])
        : "r"(a[0]), "r"(a[1]), "r"(a[2]), "r"(a[3]), "r"(b[0]), "r"(b[1]));
}
__device__ __forceinline__ void ldmat_x4(uint32_t r[4], uint32_t addr) {
    asm volatile("ldmatrix.sync.aligned.m8n8.x4.shared.b16 {%0,%1,%2,%3}, [%4];"
        : "=r"(r[0]), "=r"(r[1]), "=r"(r[2]), "=r"(r[3]) : "r"(addr));
}
__device__ __forceinline__ void lstm_pw(float si, float sf, float sc, float so,
                                        float cv, float wi, float wf, float wo,
                                        float& hh, float& cc) {
    float ig = sigmoid_f(si + wi * cv);
    float fg = sigmoid_f(sf + wf * cv);
    float tg = tanh_f(sc);
    cc = fg * cv + ig * tg;
    float og = sigmoid_f(so + wo * cc);
    hh = og * tanh_f(cc);
}

// ---------------- prep kernel ----------------
struct PrepArgs {
    const float* Wx[4];
    const float* bx[4];
    const float* Wh[4];
    const float* bh[4];
    const float* b[4];
    const float* wc[4];   // wc[2] dummy
    const float* Wl;
    const float* bl;
};

__global__ void prep_kernel(PrepArgs A) {
    const int gtid = blockIdx.x * blockDim.x + threadIdx.x;
    const int gstr = gridDim.x * blockDim.x;
    // gate B fragments in mma.m16n8k16 lane order (fp16).
    for (int idx = gtid; idx < 3072; idx += gstr) {
        int w    = idx & 1;
        int lane = (idx >> 1) & 31;
        int n    = (idx >> 6) & 15;
        int ks   = idx >> 10;
        int gatech = n * 8 + (lane >> 2);
        int g = gatech >> 5, j = gatech & 31;
        int k0 = ks * 16 + (lane & 3) * 2 + w * 8;
        uint32_t out = 0;
        for (int e = 0; e < 2; e++) {
            int k = k0 + e;
            float val = 0.f;
            if (k < FIN)      val = A.Wx[g][k * HDIM + j];
            else if (k < 40)  val = A.Wh[g][(k - FIN) * HDIM + j];
            else if (k == 40) val = A.bx[g][j] + A.bh[g][j] + A.b[g][j];
            out |= (uint32_t)__half_as_ushort(__float2half_rn(val)) << (16 * e);
        }
        g_Bfrag[idx] = out;
    }
    // y-head B fragments: Wl [32 x 9], 2 n-tiles of 8
    for (int idx = gtid; idx < 256; idx += gstr) {
        int w    = idx & 1;
        int lane = (idx >> 1) & 31;
        int ks   = (idx >> 6) & 1;
        int nt   = idx >> 7;
        int n  = nt * 8 + (lane >> 2);
        int k0 = ks * 16 + (lane & 3) * 2 + w * 8;
        uint32_t out = 0;
        for (int e = 0; e < 2; e++) {
            float val = (n < OUTD) ? A.Wl[(k0 + e) * OUTD + n] : 0.f;
            out |= (uint32_t)__half_as_ushort(__float2half_rn(val)) << (16 * e);
        }
        g_yB[idx] = out;
    }
    for (int j = gtid; j < HDIM; j += gstr) {
        g_epi.wci[j] = A.wc[0][j];
        g_epi.wcf[j] = A.wc[1][j];
        g_epi.wco[j] = A.wc[3][j];
    }
    if (gtid < 12)
        g_epi.bl[gtid] = (gtid < OUTD) ? A.bl[gtid] : 0.f;
}

// ---------------- main kernel ----------------
struct Params {
    const float* x;
    const float* h;
    const float* c;
    float* y;
    float* h0;
    float* c0;
    int N;
};

__global__ void __launch_bounds__(TPB)
gconv_lstm_mma_kernel(Params P) {
    extern __shared__ __align__(16) char smem[];
    const uint32_t sbase = smem_u32(smem);
    const int tid = threadIdx.x;

    // ---- stage B fragments, yB fragments, epilogue tables ----
    {
        const uint4* src = (const uint4*)g_Bfrag;
        uint4* dst = (uint4*)(smem + SM_B);
        for (int i = tid; i < 3072 / 4; i += TPB) dst[i] = src[i];
        if (tid < 64) ((uint4*)(smem + SM_YB))[tid] = ((const uint4*)g_yB)[tid];
        const uint32_t* es = (const uint32_t*)&g_epi;
        uint32_t* ed = (uint32_t*)(smem + SM_EPI);
        if (tid < (int)(sizeof(EpiT) / 4)) ed[tid] = es[tid];
    }

    // ---- stage this thread's node row as fp16 A (swizzled 128B rows) ----
    {
        const int sNode = blockIdx.x * NPB + tid;
        const int cls   = (sNode < P.N) ? sNode : (P.N - 1);
        float v[K48];
#pragma unroll
        for (int i = 0; i < K48; i++) v[i] = 0.f;
        const float4* xp = (const float4*)(P.x + (size_t)cls * FIN);
        float4 x0 = xp[0], x1 = xp[1];
        v[0]=x0.x; v[1]=x0.y; v[2]=x0.z; v[3]=x0.w;
        v[4]=x1.x; v[5]=x1.y; v[6]=x1.z; v[7]=x1.w;
        const float4* hp = (const float4*)(P.h + (size_t)cls * HDIM);
#pragma unroll
        for (int i = 0; i < 8; i++) {
            float4 hv = hp[i];
            v[8+4*i]=hv.x; v[9+4*i]=hv.y; v[10+4*i]=hv.z; v[11+4*i]=hv.w;
        }
        v[40] = 1.0f;   // bias column
#pragma unroll
        for (int i = 0; i < 6; i++) {
            uint32_t w[4];
#pragma unroll
            for (int p = 0; p < 4; p++)
                w[p] = pack_h2(v[i * 8 + 2 * p], v[i * 8 + 2 * p + 1]);
            uint32_t off = tid * 128 + ((i * 16) ^ ((tid & 7) << 4));
            *(uint4*)(smem + SM_A + off) = make_uint4(w[0], w[1], w[2], w[3]);
        }
    }
    __syncthreads();

    const EpiT* E = (const EpiT*)(smem + SM_EPI);
    const int lane = tid & 31, warp = tid >> 5;
    const int g = lane >> 2, q = lane & 3;

    // y-head B fragments (shared by both tiles): [nt][ks]
    uint2 yb[2][2];
#pragma unroll
    for (int nt = 0; nt < 2; nt++)
#pragma unroll
        for (int ks = 0; ks < 2; ks++)
            yb[nt][ks] = *(const uint2*)(smem + SM_YB + ((nt * 2 + ks) * 32 + lane) * 8);
    const float2 blq = *(const float2*)(&E->bl[2 * q]);
    const float  bl8 = E->bl[8];
    const float2 wiv[4] = {
        *(const float2*)(&E->wci[q*2]),      *(const float2*)(&E->wci[8 + q*2]),
        *(const float2*)(&E->wci[16 + q*2]), *(const float2*)(&E->wci[24 + q*2]) };
    const float2 wfv[4] = {
        *(const float2*)(&E->wcf[q*2]),      *(const float2*)(&E->wcf[8 + q*2]),
        *(const float2*)(&E->wcf[16 + q*2]), *(const float2*)(&E->wcf[24 + q*2]) };
    const float2 wov[4] = {
        *(const float2*)(&E->wco[q*2]),      *(const float2*)(&E->wco[8 + q*2]),
        *(const float2*)(&E->wco[16 + q*2]), *(const float2*)(&E->wco[24 + q*2]) };

#pragma unroll 1
    for (int t = 0; t < 2; t++) {
        const int rbase = warp * 32 + t * 16;      // staging row base of tile
        const int node0 = blockIdx.x * NPB + rbase + g;
        const int node1 = node0 + 8;
        const bool v0 = (node0 < P.N), v1 = (node1 < P.N);
        const int ci0 = v0 ? node0 : (P.N - 1);
        const int ci1 = v1 ? node1 : (P.N - 1);

        // ---- prefetch c (completes under the GEMM) ----
        float2 cva[4], cvb[4];
#pragma unroll
        for (int nl = 0; nl < 4; nl++) {
            const int j0 = nl * 8 + q * 2;
            cva[nl] = *(const float2*)(P.c + (size_t)ci0 * HDIM + j0);
            cvb[nl] = *(const float2*)(P.c + (size_t)ci1 * HDIM + j0);
        }

        // ---- A fragments via ldmatrix (3 per tile) ----
        uint32_t ah[3][4];
        {
            const int m = lane >> 3, rl = lane & 7;
            const int row = rbase + (m & 1) * 8 + rl;
            const int seg = m >> 1;
#pragma unroll
            for (int ks = 0; ks < 3; ks++) {
                uint32_t byte = (uint32_t)((ks * 32 + seg * 16) ^ (rl << 4));
                ldmat_x4(ah[ks], sbase + SM_A + row * 128 + byte);
            }
        }

        // ---- 16 n-steps x 3 ksteps mma ----
        float acc[16][4];
#pragma unroll
        for (int n = 0; n < 16; n++) {
            acc[n][0] = acc[n][1] = acc[n][2] = acc[n][3] = 0.f;
            uint32_t bf[3][2];
#pragma unroll
            for (int ks = 0; ks < 3; ks++) {
                uint2 hv = *(const uint2*)(smem + SM_B + ((ks*16 + n)*32 + lane)*8);
                bf[ks][0] = hv.x; bf[ks][1] = hv.y;
            }
#pragma unroll
            for (int ks = 0; ks < 3; ks++) mma16816(acc[n], ah[ks], bf[ks]);
        }

        // ---- epilogue: LSTM pointwise; pack relu(h0) into y A-fragments ----
        uint32_t yA[2][4];
        float yacc0[4] = {0.f, 0.f, 0.f, 0.f};
        float yacc1[4] = {0.f, 0.f, 0.f, 0.f};

#pragma unroll
        for (int nl = 0; nl < 4; nl++) {
            const int j0 = nl * 8 + q * 2;
            float ha, ca, hb, cb, ha2, ca2, hb2, cb2;
            lstm_pw(acc[nl][0], acc[nl+4][0], acc[nl+8][0], acc[nl+12][0],
                    cva[nl].x, wiv[nl].x, wfv[nl].x, wov[nl].x, ha, ca);
            lstm_pw(acc[nl][1], acc[nl+4][1], acc[nl+8][1], acc[nl+12][1],
                    cva[nl].y, wiv[nl].y, wfv[nl].y, wov[nl].y, hb, cb);
            lstm_pw(acc[nl][2], acc[nl+4][2], acc[nl+8][2], acc[nl+12][2],
                    cvb[nl].x, wiv[nl].x, wfv[nl].x, wov[nl].x, ha2, ca2);
            lstm_pw(acc[nl][3], acc[nl+4][3], acc[nl+8][3], acc[nl+12][3],
                    cvb[nl].y, wiv[nl].y, wfv[nl].y, wov[nl].y, hb2, cb2);
            if (v0) {
                *(float2*)(P.h0 + (size_t)node0 * HDIM + j0) = make_float2(ha, hb);
                *(float2*)(P.c0 + (size_t)node0 * HDIM + j0) = make_float2(ca, cb);
            }
            if (v1) {
                *(float2*)(P.h0 + (size_t)node1 * HDIM + j0) = make_float2(ha2, hb2);
                *(float2*)(P.c0 + (size_t)node1 * HDIM + j0) = make_float2(ca2, cb2);
            }
            // A-fragment slot: ks = nl>>1, half w = nl&1 -> regs {2w, 2w+1}
            const int ks = nl >> 1, w = nl & 1;
            yA[ks][2 * w + 0] = pack_h2(fmaxf(ha, 0.f),  fmaxf(hb, 0.f));
            yA[ks][2 * w + 1] = pack_h2(fmaxf(ha2, 0.f), fmaxf(hb2, 0.f));
        }

        // ---- y-head mma: 2 n-tiles x 2 ksteps ----
        {
            uint32_t b0[2] = {yb[0][0].x, yb[0][0].y};
            uint32_t b1[2] = {yb[0][1].x, yb[0][1].y};
            mma16816(yacc0, yA[0], b0);
            mma16816(yacc0, yA[1], b1);
            uint32_t b2[2] = {yb[1][0].x, yb[1][0].y};
            uint32_t b3[2] = {yb[1][1].x, yb[1][1].y};
            mma16816(yacc1, yA[0], b2);
            mma16816(yacc1, yA[1], b3);
        }

        // ---- scalar y stores (rows are 9 floats; float2 would misalign) ----
        if (v0) {
            float* oy = P.y + (size_t)node0 * OUTD;
            oy[2 * q]     = yacc0[0] + blq.x;
            oy[2 * q + 1] = yacc0[1] + blq.y;
            if (q == 0) oy[8] = yacc1[0] + bl8;
        }
        if (v1) {
            float* oy = P.y + (size_t)node1 * OUTD;
            oy[2 * q]     = yacc0[2] + blq.x;
            oy[2 * q + 1] = yacc0[3] + blq.y;
            if (q == 0) oy[8] = yacc1[2] + bl8;
        }
    }
}

extern "C" void kernel_launch(void* const* d_in, const int* in_sizes, int n_in,
                              void* d_out, int out_size) {
    (void)n_in; (void)out_size;

    PrepArgs A;
    const int wx_idx[4] = {5, 11, 17, 22};   // gate order: i, f, c, o
    for (int g = 0; g < 4; g++) {
        int base = wx_idx[g];
        A.Wx[g] = (const float*)d_in[base + 0];
        A.bx[g] = (const float*)d_in[base + 1];
        A.Wh[g] = (const float*)d_in[base + 2];
        A.bh[g] = (const float*)d_in[base + 3];
        A.b[g]  = (const float*)d_in[base + 4];
        A.wc[g] = (g == 2) ? A.b[g] : (const float*)d_in[base + 5];  // dummy for gate c
    }
    A.Wl = (const float*)d_in[28];
    A.bl = (const float*)d_in[29];

    Params P;
    P.x = (const float*)d_in[0];
    // d_in[1] = edge_index, d_in[2] = edge_weight: unused (ChebConv K=1)
    P.h = (const float*)d_in[3];
    P.c = (const float*)d_in[4];

    const int N = in_sizes[0] / FIN;
    P.N = N;
    float* out = (float*)d_out;
    P.y  = out;
    P.h0 = out + (size_t)N * OUTD;
    P.c0 = out + (size_t)N * (OUTD + HDIM);

    prep_kernel<<<16, 256>>>(A);

    cudaFuncSetAttribute(gconv_lstm_mma_kernel,
                         cudaFuncAttributeMaxDynamicSharedMemorySize, SM_TOTAL);
    const int grid = (N + NPB - 1) / NPB;
    gconv_lstm_mma_kernel<<<grid, TPB, SM_TOTAL>>>(P);
}

// round 11
// speedup vs baseline: 4.6871x; 1.0941x over previous
#include <cuda_runtime.h>
#include <cuda_fp16.h>
#include <cstdint>

// GConvLSTM (ChebConv K=1) fused cell + head, warp-level mma.sync fp16.
// R11: B columns gate-interleaved (col n*8+m -> gate n&3, ch (n>>2)*8+m) so
// the epilogue runs per 4-n chunk; both 16-node tiles share each B fragment
// load (mainloop B LDS halved). y-head on tensor cores, ldmatrix A frags.

#define FIN   8
#define HDIM  32
#define OUTD  9
#define TPB   128
#define NPB   128          // nodes per block
#define K48   48           // padded K (41 used: 8 x + 32 h + 1 bias)

// dynamic smem layout (bytes)
#define SM_A    0                        // 128 rows x 128B (fp16, swizzled)
#define SM_B    16384                    // 3 ks x 16 n x 32 lanes x 8B = 12288
#define SM_YB   (16384 + 12288)          // 28672: 2 nt x 2 ks x 32 x 8B = 1024
#define SM_EPI  (28672 + 1024)           // 29696
// EpiT = 3*32*4 + 12*4 = 432
#define SM_TOTAL (29696 + 432)

struct EpiT {
    float wci[HDIM], wcf[HDIM], wco[HDIM];
    float bl[12];
};
__device__ __align__(16) uint32_t g_Bfrag[3072];   // [ks][n][lane][w] fp16x2
__device__ __align__(16) uint32_t g_yB[256];       // [nt][ks][lane][w] fp16x2
__device__ __align__(16) EpiT     g_epi;

// ---------------- math helpers ----------------
__device__ __forceinline__ float fast_ex2(float x) {
    float r; asm("ex2.approx.f32 %0, %1;" : "=f"(r) : "f"(x)); return r;
}
__device__ __forceinline__ float fast_rcp(float x) {
    float r; asm("rcp.approx.f32 %0, %1;" : "=f"(r) : "f"(x)); return r;
}
__device__ __forceinline__ float sigmoid_f(float v) {
    return fast_rcp(1.0f + fast_ex2(-1.4426950408889634f * v));
}
__device__ __forceinline__ float tanh_f(float v) {
    return 1.0f - 2.0f * fast_rcp(1.0f + fast_ex2(2.8853900817779268f * v));
}
__device__ __forceinline__ uint32_t pack_h2(float f0, float f1) {
    __half h0 = __float2half_rn(f0), h1 = __float2half_rn(f1);
    return ((uint32_t)__half_as_ushort(h1) << 16) | __half_as_ushort(h0);
}
__device__ __forceinline__ uint32_t smem_u32(const void* p) {
    uint32_t a;
    asm("{ .reg .u64 t; cvta.to.shared.u64 t, %1; cvt.u32.u64 %0, t; }" : "=r"(a) : "l"(p));
    return a;
}
__device__ __forceinline__ void mma16816(float c[4], const uint32_t a[4],
                                         const uint32_t b[2]) {
    asm volatile(
        "mma.sync.aligned.m16n8k16.row.col.f32.f16.f16.f32 "
        "{%0,%1,%2,%3}, {%4,%5,%6,%7}, {%8,%9}, {%0,%1,%2,%3};"
        : "+f"(c[0]), "+f"(c[1]), "+f"(c[2]), "+f"(c[3])
        : "r"(a[0]), "r"(a[1]), "r"(a[2]), "r"(a[3]), "r"(b[0]), "r"(b[1]));
}
__device__ __forceinline__ void ldmat_x4(uint32_t r[4], uint32_t addr) {
    asm volatile("ldmatrix.sync.aligned.m8n8.x4.shared.b16 {%0,%1,%2,%3}, [%4];"
        : "=r"(r[0]), "=r"(r[1]), "=r"(r[2]), "=r"(r[3]) : "r"(addr));
}
__device__ __forceinline__ void lstm_pw(float si, float sf, float sc, float so,
                                        float cv, float wi, float wf, float wo,
                                        float& hh, float& cc) {
    float ig = sigmoid_f(si + wi * cv);
    float fg = sigmoid_f(sf + wf * cv);
    float tg = tanh_f(sc);
    cc = fg * cv + ig * tg;
    float og = sigmoid_f(so + wo * cc);
    hh = og * tanh_f(cc);
}

// ---------------- prep kernel ----------------
struct PrepArgs {
    const float* Wx[4];
    const float* bx[4];
    const float* Wh[4];
    const float* bh[4];
    const float* b[4];
    const float* wc[4];   // wc[2] dummy
    const float* Wl;
    const float* bl;
};

__global__ void prep_kernel(PrepArgs A) {
    const int gtid = blockIdx.x * blockDim.x + threadIdx.x;
    const int gstr = gridDim.x * blockDim.x;
    // gate B fragments, mma.m16n8k16 lane order, gate-interleaved columns:
    // column n*8+m -> gate = n&3, channel j = (n>>2)*8 + m
    for (int idx = gtid; idx < 3072; idx += gstr) {
        int w    = idx & 1;
        int lane = (idx >> 1) & 31;
        int n    = (idx >> 6) & 15;
        int ks   = idx >> 10;
        int g = n & 3;
        int j = (n >> 2) * 8 + (lane >> 2);
        int k0 = ks * 16 + (lane & 3) * 2 + w * 8;
        uint32_t out = 0;
        for (int e = 0; e < 2; e++) {
            int k = k0 + e;
            float val = 0.f;
            if (k < FIN)      val = A.Wx[g][k * HDIM + j];
            else if (k < 40)  val = A.Wh[g][(k - FIN) * HDIM + j];
            else if (k == 40) val = A.bx[g][j] + A.bh[g][j] + A.b[g][j];
            out |= (uint32_t)__half_as_ushort(__float2half_rn(val)) << (16 * e);
        }
        g_Bfrag[idx] = out;
    }
    // y-head B fragments: Wl [32 x 9], 2 n-tiles of 8
    for (int idx = gtid; idx < 256; idx += gstr) {
        int w    = idx & 1;
        int lane = (idx >> 1) & 31;
        int ks   = (idx >> 6) & 1;
        int nt   = idx >> 7;
        int n  = nt * 8 + (lane >> 2);
        int k0 = ks * 16 + (lane & 3) * 2 + w * 8;
        uint32_t out = 0;
        for (int e = 0; e < 2; e++) {
            float val = (n < OUTD) ? A.Wl[(k0 + e) * OUTD + n] : 0.f;
            out |= (uint32_t)__half_as_ushort(__float2half_rn(val)) << (16 * e);
        }
        g_yB[idx] = out;
    }
    for (int j = gtid; j < HDIM; j += gstr) {
        g_epi.wci[j] = A.wc[0][j];
        g_epi.wcf[j] = A.wc[1][j];
        g_epi.wco[j] = A.wc[3][j];
    }
    if (gtid < 12)
        g_epi.bl[gtid] = (gtid < OUTD) ? A.bl[gtid] : 0.f;
}

// ---------------- main kernel ----------------
struct Params {
    const float* x;
    const float* h;
    const float* c;
    float* y;
    float* h0;
    float* c0;
    int N;
};

__global__ void __launch_bounds__(TPB, 4)
gconv_lstm_mma_kernel(Params P) {
    extern __shared__ __align__(16) char smem[];
    const uint32_t sbase = smem_u32(smem);
    const int tid = threadIdx.x;

    // ---- stage B fragments, yB fragments, epilogue tables ----
    {
        const uint4* src = (const uint4*)g_Bfrag;
        uint4* dst = (uint4*)(smem + SM_B);
        for (int i = tid; i < 3072 / 4; i += TPB) dst[i] = src[i];
        if (tid < 64) ((uint4*)(smem + SM_YB))[tid] = ((const uint4*)g_yB)[tid];
        const uint32_t* es = (const uint32_t*)&g_epi;
        uint32_t* ed = (uint32_t*)(smem + SM_EPI);
        if (tid < (int)(sizeof(EpiT) / 4)) ed[tid] = es[tid];
    }

    // ---- stage this thread's node row as fp16 A (swizzled 128B rows) ----
    {
        const int sNode = blockIdx.x * NPB + tid;
        const int cls   = (sNode < P.N) ? sNode : (P.N - 1);
        float v[K48];
#pragma unroll
        for (int i = 0; i < K48; i++) v[i] = 0.f;
        const float4* xp = (const float4*)(P.x + (size_t)cls * FIN);
        float4 x0 = xp[0], x1 = xp[1];
        v[0]=x0.x; v[1]=x0.y; v[2]=x0.z; v[3]=x0.w;
        v[4]=x1.x; v[5]=x1.y; v[6]=x1.z; v[7]=x1.w;
        const float4* hp = (const float4*)(P.h + (size_t)cls * HDIM);
#pragma unroll
        for (int i = 0; i < 8; i++) {
            float4 hv = hp[i];
            v[8+4*i]=hv.x; v[9+4*i]=hv.y; v[10+4*i]=hv.z; v[11+4*i]=hv.w;
        }
        v[40] = 1.0f;   // bias column
#pragma unroll
        for (int i = 0; i < 6; i++) {
            uint32_t w[4];
#pragma unroll
            for (int p = 0; p < 4; p++)
                w[p] = pack_h2(v[i * 8 + 2 * p], v[i * 8 + 2 * p + 1]);
            uint32_t off = tid * 128 + ((i * 16) ^ ((tid & 7) << 4));
            *(uint4*)(smem + SM_A + off) = make_uint4(w[0], w[1], w[2], w[3]);
        }
    }
    __syncthreads();

    const EpiT* E = (const EpiT*)(smem + SM_EPI);
    const int lane = tid & 31, warp = tid >> 5;
    const int g = lane >> 2, q = lane & 3;

    // node bases per tile (t in {0,1}); node0 = nA[t], node1 = nA[t] + 8
    int nA[2];
    nA[0] = blockIdx.x * NPB + warp * 32 + g;
    nA[1] = nA[0] + 16;
    bool v0[2], v1[2];
    int ci0[2], ci1[2];
#pragma unroll
    for (int t = 0; t < 2; t++) {
        v0[t] = (nA[t] < P.N);
        v1[t] = (nA[t] + 8 < P.N);
        ci0[t] = v0[t] ? nA[t] : (P.N - 1);
        ci1[t] = v1[t] ? (nA[t] + 8) : (P.N - 1);
    }

    // ---- A fragments via ldmatrix (both tiles, persistent) ----
    uint32_t ah[2][3][4];
    {
        const int m = lane >> 3, rl = lane & 7;
        const int seg = m >> 1;
#pragma unroll
        for (int t = 0; t < 2; t++) {
            const int row = warp * 32 + t * 16 + (m & 1) * 8 + rl;
#pragma unroll
            for (int ks = 0; ks < 3; ks++) {
                uint32_t byte = (uint32_t)((ks * 32 + seg * 16) ^ (rl << 4));
                ldmat_x4(ah[t][ks], sbase + SM_A + row * 128 + byte);
            }
        }
    }

    uint32_t yA[2][2][4];   // per tile: y-head A fragments (filled per chunk)

#pragma unroll
    for (int cg = 0; cg < 4; cg++) {
        const int j0 = cg * 8 + q * 2;

        // c loads for this chunk (latency hidden under the chunk's mmas)
        float2 cva[2], cvb[2];
#pragma unroll
        for (int t = 0; t < 2; t++) {
            cva[t] = *(const float2*)(P.c + (size_t)ci0[t] * HDIM + j0);
            cvb[t] = *(const float2*)(P.c + (size_t)ci1[t] * HDIM + j0);
        }

        // B fragments for the chunk's 4 n-steps (shared by both tiles)
        uint32_t bf[4][3][2];
#pragma unroll
        for (int gi = 0; gi < 4; gi++)
#pragma unroll
            for (int ks = 0; ks < 3; ks++) {
                uint2 hv = *(const uint2*)(smem + SM_B +
                            ((ks * 16 + cg * 4 + gi) * 32 + lane) * 8);
                bf[gi][ks][0] = hv.x; bf[gi][ks][1] = hv.y;
            }

        // mma: acc[tile][gate][4]
        float acc[2][4][4];
#pragma unroll
        for (int t = 0; t < 2; t++)
#pragma unroll
            for (int gi = 0; gi < 4; gi++) {
                acc[t][gi][0] = acc[t][gi][1] = acc[t][gi][2] = acc[t][gi][3] = 0.f;
#pragma unroll
                for (int ks = 0; ks < 3; ks++)
                    mma16816(acc[t][gi], ah[t][ks], bf[gi][ks]);
            }

        // peephole weights for this chunk's channels
        const float2 wiv = *(const float2*)(&E->wci[j0]);
        const float2 wfv = *(const float2*)(&E->wcf[j0]);
        const float2 wov = *(const float2*)(&E->wco[j0]);
        const int ks = cg >> 1, w = cg & 1;

#pragma unroll
        for (int t = 0; t < 2; t++) {
            float ha, ca, hb, cb, ha2, ca2, hb2, cb2;
            lstm_pw(acc[t][0][0], acc[t][1][0], acc[t][2][0], acc[t][3][0],
                    cva[t].x, wiv.x, wfv.x, wov.x, ha, ca);
            lstm_pw(acc[t][0][1], acc[t][1][1], acc[t][2][1], acc[t][3][1],
                    cva[t].y, wiv.y, wfv.y, wov.y, hb, cb);
            lstm_pw(acc[t][0][2], acc[t][1][2], acc[t][2][2], acc[t][3][2],
                    cvb[t].x, wiv.x, wfv.x, wov.x, ha2, ca2);
            lstm_pw(acc[t][0][3], acc[t][1][3], acc[t][2][3], acc[t][3][3],
                    cvb[t].y, wiv.y, wfv.y, wov.y, hb2, cb2);
            if (v0[t]) {
                *(float2*)(P.h0 + (size_t)nA[t] * HDIM + j0) = make_float2(ha, hb);
                *(float2*)(P.c0 + (size_t)nA[t] * HDIM + j0) = make_float2(ca, cb);
            }
            if (v1[t]) {
                *(float2*)(P.h0 + (size_t)(nA[t] + 8) * HDIM + j0) = make_float2(ha2, hb2);
                *(float2*)(P.c0 + (size_t)(nA[t] + 8) * HDIM + j0) = make_float2(ca2, cb2);
            }
            yA[t][ks][2 * w + 0] = pack_h2(fmaxf(ha, 0.f),  fmaxf(hb, 0.f));
            yA[t][ks][2 * w + 1] = pack_h2(fmaxf(ha2, 0.f), fmaxf(hb2, 0.f));
        }
    }

    // ---- y-head mma: per tile, 2 n-tiles x 2 ksteps ----
    const float2 blq = *(const float2*)(&E->bl[2 * q]);
    const float  bl8 = E->bl[8];
#pragma unroll
    for (int t = 0; t < 2; t++) {
        float yacc0[4] = {0.f, 0.f, 0.f, 0.f};
        float yacc1[4] = {0.f, 0.f, 0.f, 0.f};
#pragma unroll
        for (int ks = 0; ks < 2; ks++) {
            uint2 b0 = *(const uint2*)(smem + SM_YB + ((0 * 2 + ks) * 32 + lane) * 8);
            uint2 b1 = *(const uint2*)(smem + SM_YB + ((1 * 2 + ks) * 32 + lane) * 8);
            uint32_t bb0[2] = {b0.x, b0.y};
            uint32_t bb1[2] = {b1.x, b1.y};
            mma16816(yacc0, yA[t][ks], bb0);
            mma16816(yacc1, yA[t][ks], bb1);
        }
        if (v0[t]) {
            float* oy = P.y + (size_t)nA[t] * OUTD;
            oy[2 * q]     = yacc0[0] + blq.x;
            oy[2 * q + 1] = yacc0[1] + blq.y;
            if (q == 0) oy[8] = yacc1[0] + bl8;
        }
        if (v1[t]) {
            float* oy = P.y + (size_t)(nA[t] + 8) * OUTD;
            oy[2 * q]     = yacc0[2] + blq.x;
            oy[2 * q + 1] = yacc0[3] + blq.y;
            if (q == 0) oy[8] = yacc1[2] + bl8;
        }
    }
}

extern "C" void kernel_launch(void* const* d_in, const int* in_sizes, int n_in,
                              void* d_out, int out_size) {
    (void)n_in; (void)out_size;

    PrepArgs A;
    const int wx_idx[4] = {5, 11, 17, 22};   // gate order: i, f, c, o
    for (int g = 0; g < 4; g++) {
        int base = wx_idx[g];
        A.Wx[g] = (const float*)d_in[base + 0];
        A.bx[g] = (const float*)d_in[base + 1];
        A.Wh[g] = (const float*)d_in[base + 2];
        A.bh[g] = (const float*)d_in[base + 3];
        A.b[g]  = (const float*)d_in[base + 4];
        A.wc[g] = (g == 2) ? A.b[g] : (const float*)d_in[base + 5];  // dummy for gate c
    }
    A.Wl = (const float*)d_in[28];
    A.bl = (const float*)d_in[29];

    Params P;
    P.x = (const float*)d_in[0];
    // d_in[1] = edge_index, d_in[2] = edge_weight: unused (ChebConv K=1)
    P.h = (const float*)d_in[3];
    P.c = (const float*)d_in[4];

    const int N = in_sizes[0] / FIN;
    P.N = N;
    float* out = (float*)d_out;
    P.y  = out;
    P.h0 = out + (size_t)N * OUTD;
    P.c0 = out + (size_t)N * (OUTD + HDIM);

    prep_kernel<<<16, 256>>>(A);

    cudaFuncSetAttribute(gconv_lstm_mma_kernel,
                         cudaFuncAttributeMaxDynamicSharedMemorySize, SM_TOTAL);
    const int grid = (N + NPB - 1) / NPB;
    gconv_lstm_mma_kernel<<<grid, TPB, SM_TOTAL>>>(P);
}